// round 8
// baseline (speedup 1.0000x reference)
#include <cuda_runtime.h>
#include <math.h>

// Problem constants (fixed shapes per reference)
#define B_EV   20
#define V_EV   3000
#define KNN_K  40
#define FIN    64
#define PROP   64
#define DIM    4
#define FOUT   128
#define NHITS  (B_EV * V_EV)        // 60000
#define AIN    (2 * PROP + FIN)     // 192

typedef unsigned long long ull;

// Scratch (device globals; no allocations allowed)
__device__ float g_feat[NHITS * PROP];       // relu(x@W_prop+b) [N,64]
__device__ float g_coords[NHITS * DIM];      // x@W_sp+b         [N,4] (AoS)
__device__ __align__(16) float g_cx[NHITS];  // SoA coords + norm (16B-aligned)
__device__ __align__(16) float g_cy[NHITS];
__device__ __align__(16) float g_cz[NHITS];
__device__ __align__(16) float g_cw[NHITS];
__device__ __align__(16) float g_cn[NHITS];
__device__ int   g_nidx[NHITS * KNN_K];      // global neighbor idx
__device__ float g_dist[NHITS * KNN_K];      // clamped distsq
__device__ float g_a[(size_t)NHITS * AIN];   // GEMM input [N,192]

// ---- packed f32x2 helpers ----
__device__ __forceinline__ ull f2_mul(ull a, ull b) {
    ull r; asm("mul.rn.f32x2 %0, %1, %2;" : "=l"(r) : "l"(a), "l"(b)); return r;
}
__device__ __forceinline__ ull f2_add(ull a, ull b) {
    ull r; asm("add.rn.f32x2 %0, %1, %2;" : "=l"(r) : "l"(a), "l"(b)); return r;
}
__device__ __forceinline__ ull f2_fma(ull a, ull b, ull c) {
    ull r; asm("fma.rn.f32x2 %0, %1, %2, %3;" : "=l"(r) : "l"(a), "l"(b), "l"(c)); return r;
}
__device__ __forceinline__ ull f2_bcast(float a) {
    ull r; asm("mov.b64 %0, {%1, %1};" : "=l"(r) : "f"(a)); return r;
}
__device__ __forceinline__ void f2_unpack(ull v, float& a, float& b) {
    asm("mov.b64 {%0, %1}, %2;" : "=f"(a), "=f"(b) : "l"(v));
}
// 16-byte async copy global->shared
__device__ __forceinline__ void cp16(void* smem_ptr, const void* gptr) {
    unsigned int sa = (unsigned int)__cvta_generic_to_shared(smem_ptr);
    asm volatile("cp.async.cg.shared.global [%0], [%1], 16;" :: "r"(sa), "l"(gptr));
}

// ---------------------------------------------------------------------------
// K1: coordinates = x@W_sp + b_sp ; feat = relu(x@W_prop + b_prop)
// ---------------------------------------------------------------------------
__global__ __launch_bounds__(256)
void k_transform(const float* __restrict__ x,
                 const float* __restrict__ Wp, const float* __restrict__ bp,
                 const float* __restrict__ Ws, const float* __restrict__ bs,
                 float* __restrict__ coords_out)  // may be null
{
    __shared__ float xs[4][FIN];
    int h = threadIdx.x >> 6;
    int j = threadIdx.x & 63;
    int hit = blockIdx.x * 4 + h;
    if (hit < NHITS) xs[h][j] = x[hit * FIN + j];
    __syncthreads();
    if (hit >= NHITS) return;

    float acc = bp[j];
#pragma unroll
    for (int i = 0; i < FIN; i++)
        acc += xs[h][i] * Wp[i * PROP + j];
    g_feat[hit * PROP + j] = fmaxf(acc, 0.0f);

    if (j < DIM) {
        float c = bs[j];
#pragma unroll
        for (int i = 0; i < FIN; i++)
            c += xs[h][i] * Ws[i * DIM + j];
        g_coords[hit * DIM + j] = c;
        if (coords_out) coords_out[hit * DIM + j] = c;
    }
}

// AoS -> SoA + per-hit norm (same FMA grouping as KNN math)
__global__ __launch_bounds__(256)
void k_soa()
{
    int i = blockIdx.x * 256 + threadIdx.x;
    if (i >= NHITS) return;
    float4 c = *(const float4*)&g_coords[(size_t)i * 4];
    g_cx[i] = c.x; g_cy[i] = c.y; g_cz[i] = c.z; g_cw[i] = c.w;
    g_cn[i] = ((c.x * c.x + c.y * c.y) + c.z * c.z) + c.w * c.w;
}

// ---------------------------------------------------------------------------
// K2: per-event exact KNN. Candidates staged through double-buffered shared
// tiles via cp.async (hides L2 latency); hot loop = packed f32x2 math over
// LDS broadcasts + float-domain filter into a per-lane ring; ring flushed
// into a per-thread 4-ary shared max-heap (exact 64-bit recheck + self skip).
// ---------------------------------------------------------------------------
#define KNN_T    64    // threads per block
#define RING_CAP 8
#define TILE     256
#define NTILES   ((V_EV + TILE - 1) / TILE)   // 12

__device__ __forceinline__ ull heap_replace(ull (*hp)[KNN_T], int tid, ull key)
{
    int s = 0;
    ull rootval = key;
#pragma unroll
    for (int lvl = 0; lvl < 3; lvl++) {
        int c0 = 4 * s + 1;
        if (c0 >= KNN_K) break;
        ull k0 = hp[c0][tid];
        ull k1 = (c0 + 1 < KNN_K) ? hp[c0 + 1][tid] : 0ull;
        ull k2 = (c0 + 2 < KNN_K) ? hp[c0 + 2][tid] : 0ull;
        ull k3 = (c0 + 3 < KNN_K) ? hp[c0 + 3][tid] : 0ull;
        int ci = c0; ull ck = k0;
        if (k1 > ck) { ck = k1; ci = c0 + 1; }
        if (k2 > ck) { ck = k2; ci = c0 + 2; }
        if (k3 > ck) { ck = k3; ci = c0 + 3; }
        if (ck > key) {
            hp[s][tid] = ck;
            if (lvl == 0) rootval = ck;
            s = ci;
        } else break;
    }
    hp[s][tid] = key;
    return rootval;
}

__device__ __forceinline__ void heap_sift(ull (*hp)[KNN_T], int tid, ull key, int n)
{
    int s = 0;
    while (true) {
        int c0 = 4 * s + 1;
        if (c0 >= n) break;
        ull k0 = hp[c0][tid];
        ull k1 = (c0 + 1 < n) ? hp[c0 + 1][tid] : 0ull;
        ull k2 = (c0 + 2 < n) ? hp[c0 + 2][tid] : 0ull;
        ull k3 = (c0 + 3 < n) ? hp[c0 + 3][tid] : 0ull;
        int ci = c0; ull ck = k0;
        if (k1 > ck) { ck = k1; ci = c0 + 1; }
        if (k2 > ck) { ck = k2; ci = c0 + 2; }
        if (k3 > ck) { ck = k3; ci = c0 + 3; }
        if (ck > key) { hp[s][tid] = ck; s = ci; }
        else break;
    }
    hp[s][tid] = key;
}

// unflip: recover float bits from order-flipped encoding
__device__ __forceinline__ float key_to_dist(unsigned int b)
{
    unsigned int m = (unsigned int)((int)b >> 31);
    b ^= (m & 0x80000000u) | (~m);
    return __uint_as_float(b);
}

__global__ __launch_bounds__(KNN_T)
void k_knn(float* __restrict__ nidx_out,   // may be null (float-cast indices)
           float* __restrict__ dist_out)   // may be null
{
    __shared__ ull hp[KNN_K][KNN_T];                   // 20480 B
    __shared__ ull ring[RING_CAP][KNN_T];              //  4096 B
    __shared__ __align__(16) float tile[2][5][TILE];   // 10240 B  (total 34816)

    int ev   = blockIdx.y;
    int base = ev * V_EV;
    int tid  = threadIdx.x;
    int q    = blockIdx.x * KNN_T + tid;
    bool act = (q < V_EV);

#pragma unroll
    for (int k = 0; k < KNN_K; k++) hp[k][tid] = ~0ull;

    const float* px = &g_cx[base];
    const float* py = &g_cy[base];
    const float* pz = &g_cz[base];
    const float* pw = &g_cw[base];
    const float* pn = &g_cn[base];

    float qx = act ? __ldg(px + q) : 0.f;
    float qy = act ? __ldg(py + q) : 0.f;
    float qz = act ? __ldg(pz + q) : 0.f;
    float qw = act ? __ldg(pw + q) : 0.f;
    float qs = act ? __ldg(pn + q) : 0.f;

    ull qx2 = f2_bcast(qx), qy2 = f2_bcast(qy);
    ull qz2 = f2_bcast(qz), qw2 = f2_bcast(qw);
    ull qs2 = f2_bcast(qs);
    ull m2  = f2_bcast(-2.0f);

    ull   thr   = ~0ull;                      // exact 64-bit threshold (heap root)
    float thr_f = act ? INFINITY : -INFINITY; // float-domain filter threshold
    int   pend  = 0;

    // issue tile 0 (each thread loads 16B from each of the 5 arrays)
    {
        int idx = 0 * TILE + tid * 4;
        int cl = idx > V_EV - 4 ? V_EV - 4 : idx;
        cp16(&tile[0][0][tid * 4], px + cl);
        cp16(&tile[0][1][tid * 4], py + cl);
        cp16(&tile[0][2][tid * 4], pz + cl);
        cp16(&tile[0][3][tid * 4], pw + cl);
        cp16(&tile[0][4][tid * 4], pn + cl);
        asm volatile("cp.async.commit_group;");
    }

    for (int t = 0; t < NTILES; t++) {
        int b = t & 1;
        if (t + 1 < NTILES) {
            int idx = (t + 1) * TILE + tid * 4;
            int cl = idx > V_EV - 4 ? V_EV - 4 : idx;
            int nb = (t + 1) & 1;
            cp16(&tile[nb][0][tid * 4], px + cl);
            cp16(&tile[nb][1][tid * 4], py + cl);
            cp16(&tile[nb][2][tid * 4], pz + cl);
            cp16(&tile[nb][3][tid * 4], pw + cl);
            cp16(&tile[nb][4][tid * 4], pn + cl);
            asm volatile("cp.async.commit_group;");
            asm volatile("cp.async.wait_group 1;");
        } else {
            asm volatile("cp.async.wait_group 0;");
        }
        __syncthreads();   // tile[b] visible to all

        int wbase = t * TILE;
        int cnt = V_EV - wbase; if (cnt > TILE) cnt = TILE;
        const float* tcx = tile[b][0];
        const float* tcy = tile[b][1];
        const float* tcz = tile[b][2];
        const float* tcw = tile[b][3];
        const float* tcn = tile[b][4];

        for (int j = 0; j < cnt; j += 4) {
            ulonglong2 X = *(const ulonglong2*)(tcx + j);
            ulonglong2 Y = *(const ulonglong2*)(tcy + j);
            ulonglong2 Z = *(const ulonglong2*)(tcz + j);
            ulonglong2 W = *(const ulonglong2*)(tcw + j);
            ulonglong2 N = *(const ulonglong2*)(tcn + j);

            ull dot01 = f2_mul(qx2, X.x);
            dot01 = f2_fma(qy2, Y.x, dot01);
            dot01 = f2_fma(qz2, Z.x, dot01);
            dot01 = f2_fma(qw2, W.x, dot01);
            ull d01 = f2_fma(m2, dot01, f2_add(qs2, N.x));

            ull dot23 = f2_mul(qx2, X.y);
            dot23 = f2_fma(qy2, Y.y, dot23);
            dot23 = f2_fma(qz2, Z.y, dot23);
            dot23 = f2_fma(qw2, W.y, dot23);
            ull d23 = f2_fma(m2, dot23, f2_add(qs2, N.y));

            float d0, d1, d2, d3;
            f2_unpack(d01, d0, d1);
            f2_unpack(d23, d2, d3);

#pragma unroll
            for (int u = 0; u < 4; u++) {
                float d = (u == 0) ? d0 : (u == 1) ? d1 : (u == 2) ? d2 : d3;
                if (d <= thr_f) {                 // rare path: pack + append
                    unsigned int bb = __float_as_uint(d);
                    bb ^= (unsigned int)(((int)bb >> 31) | 0x80000000);
                    ring[pend][tid] = ((ull)bb << 32) | (unsigned int)(wbase + j + u);
                    pend++;
                }
            }

            if (__any_sync(0xffffffffu, pend > RING_CAP - 4)) {
#pragma unroll 1
                for (int l = 0; l < pend; l++) {
                    ull key = ring[l][tid];
                    if ((unsigned int)key == (unsigned int)q) continue;  // self
                    if (key < thr) thr = heap_replace(hp, tid, key);
                }
                pend = 0;
                thr_f = (!act) ? -INFINITY
                      : (thr == ~0ull) ? INFINITY
                      : key_to_dist((unsigned int)(thr >> 32));
            }
        }
        __syncthreads();   // done reading tile[b] before it is overwritten
    }

    // final flush
#pragma unroll 1
    for (int l = 0; l < pend; l++) {
        ull key = ring[l][tid];
        if ((unsigned int)key == (unsigned int)q) continue;
        if (key < thr) thr = heap_replace(hp, tid, key);
    }

    if (!act) return;

    // heapsort -> hp[0..39] ascending by (dist, idx)
    for (int n = KNN_K - 1; n > 0; n--) {
        ull top  = hp[0][tid];
        ull last = hp[n][tid];
        hp[n][tid] = top;
        heap_sift(hp, tid, last, n);
    }

    size_t rowoff = (size_t)(base + q) * KNN_K;
#pragma unroll 8
    for (int k = 0; k < KNN_K; k++) {
        ull key = hp[k][tid];
        unsigned int widx = (unsigned int)key;
        float dd = fmaxf(key_to_dist((unsigned int)(key >> 32)), 0.0f);
        int gidx = base + (int)widx;
        g_nidx[rowoff + k] = gidx;
        g_dist[rowoff + k] = dd;
        if (nidx_out) nidx_out[rowoff + k] = (float)gidx;
        if (dist_out) dist_out[rowoff + k] = dd;
    }
}

// ---------------------------------------------------------------------------
// K3: aggregation. a = [mean_k(f_nbr*w)-f, max_k(f_nbr*w)-f, x]  [N,192]
// ---------------------------------------------------------------------------
__global__ __launch_bounds__(256)
void k_agg(const float* __restrict__ x)
{
    __shared__ float wsh[4][KNN_K];
    __shared__ int   nsh[4][KNN_K];
    int h = threadIdx.x >> 6;
    int p = threadIdx.x & 63;
    int hit = blockIdx.x * 4 + h;

    if (hit < NHITS && p < KNN_K) {
        float dd = g_dist[(size_t)hit * KNN_K + p];
        wsh[h][p] = expf(-10.0f * dd);
        nsh[h][p] = g_nidx[(size_t)hit * KNN_K + p];
    }
    __syncthreads();
    if (hit >= NHITS) return;

    float acc = 0.0f;
    float mx = -INFINITY;
#pragma unroll 8
    for (int k = 0; k < KNN_K; k++) {
        float f = g_feat[(size_t)nsh[h][k] * PROP + p];
        float v = f * wsh[h][k];
        acc += v;
        mx = fmaxf(mx, v);
    }
    float fs = g_feat[(size_t)hit * PROP + p];
    float* arow = &g_a[(size_t)hit * AIN];
    arow[p]        = acc / (float)KNN_K - fs;
    arow[PROP + p] = mx - fs;
    arow[2 * PROP + p] = x[hit * FIN + p];
}

// ---------------------------------------------------------------------------
// K4: out = tanh(a @ W_out + b_out), [60000,192] x [192,128].
// ---------------------------------------------------------------------------
#define GM 128
#define GK 16

__global__ __launch_bounds__(256)
void k_gemm(const float* __restrict__ W, const float* __restrict__ bias,
            float* __restrict__ out)
{
    __shared__ float As[GK][GM + 4];
    __shared__ float Bs[GK][FOUT];

    int tid = threadIdx.x;
    int tx = tid & 15;
    int ty = tid >> 4;
    int rowBase = blockIdx.x * GM;

    float acc[8][8];
#pragma unroll
    for (int i = 0; i < 8; i++)
#pragma unroll
        for (int j = 0; j < 8; j++) acc[i][j] = 0.0f;

    for (int kt = 0; kt < AIN; kt += GK) {
#pragma unroll
        for (int l = 0; l < 2; l++) {
            int id = tid + l * 256;
            int r = id >> 2;
            int c4 = (id & 3) * 4;
            int grow = rowBase + r;
            float4 v = make_float4(0.f, 0.f, 0.f, 0.f);
            if (grow < NHITS)
                v = *(const float4*)&g_a[(size_t)grow * AIN + kt + c4];
            As[c4 + 0][r] = v.x;
            As[c4 + 1][r] = v.y;
            As[c4 + 2][r] = v.z;
            As[c4 + 3][r] = v.w;
        }
#pragma unroll
        for (int l = 0; l < 2; l++) {
            int id = tid + l * 256;
            int r = id >> 5;
            int c = (id & 31) * 4;
            *(float4*)&Bs[r][c] = *(const float4*)&W[(size_t)(kt + r) * FOUT + c];
        }
        __syncthreads();

#pragma unroll
        for (int k = 0; k < GK; k++) {
            float4 a0 = *(const float4*)&As[k][ty * 8];
            float4 a1 = *(const float4*)&As[k][ty * 8 + 4];
            float4 b0 = *(const float4*)&Bs[k][tx * 8];
            float4 b1 = *(const float4*)&Bs[k][tx * 8 + 4];
            float a[8] = {a0.x, a0.y, a0.z, a0.w, a1.x, a1.y, a1.z, a1.w};
            float b[8] = {b0.x, b0.y, b0.z, b0.w, b1.x, b1.y, b1.z, b1.w};
#pragma unroll
            for (int i = 0; i < 8; i++)
#pragma unroll
                for (int j = 0; j < 8; j++)
                    acc[i][j] += a[i] * b[j];
        }
        __syncthreads();
    }

    float bv[8];
#pragma unroll
    for (int j = 0; j < 8; j++) bv[j] = bias[tx * 8 + j];

#pragma unroll
    for (int i = 0; i < 8; i++) {
        int grow = rowBase + ty * 8 + i;
        if (grow < NHITS) {
#pragma unroll
            for (int j = 0; j < 8; j++)
                out[(size_t)grow * FOUT + tx * 8 + j] = tanhf(acc[i][j] + bv[j]);
        }
    }
}

// ---------------------------------------------------------------------------
// launch
// ---------------------------------------------------------------------------
extern "C" void kernel_launch(void* const* d_in, const int* in_sizes, int n_in,
                              void* d_out, int out_size)
{
    const float* x  = (const float*)d_in[0];
    const float* Wp = (const float*)d_in[2];
    const float* bp = (const float*)d_in[3];
    const float* Ws = (const float*)d_in[4];
    const float* bs = (const float*)d_in[5];
    const float* Wo = (const float*)d_in[6];
    const float* bo = (const float*)d_in[7];

    float* out = (float*)d_out;

    const int full_sz = NHITS * (FOUT + DIM + KNN_K + KNN_K);
    bool full = (out_size == full_sz);
    float* coords_out = full ? out + (size_t)NHITS * FOUT : nullptr;
    float* nidx_out   = full ? coords_out + (size_t)NHITS * DIM : nullptr;
    float* dist_out   = full ? nidx_out + (size_t)NHITS * KNN_K : nullptr;

    k_transform<<<NHITS / 4, 256>>>(x, Wp, bp, Ws, bs, coords_out);
    k_soa<<<(NHITS + 255) / 256, 256>>>();
    k_knn<<<dim3((V_EV + KNN_T - 1) / KNN_T, B_EV), KNN_T>>>(nidx_out, dist_out);
    k_agg<<<NHITS / 4, 256>>>(x);
    k_gemm<<<(NHITS + GM - 1) / GM, 256>>>(Wo, bo, out);
}

// round 9
// speedup vs baseline: 1.0419x; 1.0419x over previous
#include <cuda_runtime.h>
#include <math.h>

// Problem constants (fixed shapes per reference)
#define B_EV   20
#define V_EV   3000
#define KNN_K  40
#define FIN    64
#define PROP   64
#define DIM    4
#define FOUT   128
#define NHITS  (B_EV * V_EV)        // 60000
#define AIN    (2 * PROP + FIN)     // 192

typedef unsigned long long ull;

// Scratch (device globals; no allocations allowed)
__device__ float g_feat[NHITS * PROP];       // relu(x@W_prop+b) [N,64]
__device__ float g_coords[NHITS * DIM];      // x@W_sp+b         [N,4] (AoS)
__device__ __align__(16) float g_cx[NHITS];  // SoA coords + norm (16B-aligned)
__device__ __align__(16) float g_cy[NHITS];
__device__ __align__(16) float g_cz[NHITS];
__device__ __align__(16) float g_cw[NHITS];
__device__ __align__(16) float g_cn[NHITS];
__device__ int   g_nidx[NHITS * KNN_K];      // global neighbor idx
__device__ float g_dist[NHITS * KNN_K];      // clamped distsq
__device__ float g_a[(size_t)NHITS * AIN];   // GEMM input [N,192]

// ---- packed f32x2 helpers ----
__device__ __forceinline__ ull f2_mul(ull a, ull b) {
    ull r; asm("mul.rn.f32x2 %0, %1, %2;" : "=l"(r) : "l"(a), "l"(b)); return r;
}
__device__ __forceinline__ ull f2_add(ull a, ull b) {
    ull r; asm("add.rn.f32x2 %0, %1, %2;" : "=l"(r) : "l"(a), "l"(b)); return r;
}
__device__ __forceinline__ ull f2_fma(ull a, ull b, ull c) {
    ull r; asm("fma.rn.f32x2 %0, %1, %2, %3;" : "=l"(r) : "l"(a), "l"(b), "l"(c)); return r;
}
__device__ __forceinline__ ull f2_bcast(float a) {
    ull r; asm("mov.b64 %0, {%1, %1};" : "=l"(r) : "f"(a)); return r;
}
__device__ __forceinline__ void f2_unpack(ull v, float& a, float& b) {
    asm("mov.b64 {%0, %1}, %2;" : "=f"(a), "=f"(b) : "l"(v));
}

// ---------------------------------------------------------------------------
// K1: coordinates = x@W_sp + b_sp ; feat = relu(x@W_prop + b_prop)
// ---------------------------------------------------------------------------
__global__ __launch_bounds__(256)
void k_transform(const float* __restrict__ x,
                 const float* __restrict__ Wp, const float* __restrict__ bp,
                 const float* __restrict__ Ws, const float* __restrict__ bs,
                 float* __restrict__ coords_out)  // may be null
{
    __shared__ float xs[4][FIN];
    int h = threadIdx.x >> 6;
    int j = threadIdx.x & 63;
    int hit = blockIdx.x * 4 + h;
    if (hit < NHITS) xs[h][j] = x[hit * FIN + j];
    __syncthreads();
    if (hit >= NHITS) return;

    float acc = bp[j];
#pragma unroll
    for (int i = 0; i < FIN; i++)
        acc += xs[h][i] * Wp[i * PROP + j];
    g_feat[hit * PROP + j] = fmaxf(acc, 0.0f);

    if (j < DIM) {
        float c = bs[j];
#pragma unroll
        for (int i = 0; i < FIN; i++)
            c += xs[h][i] * Ws[i * DIM + j];
        g_coords[hit * DIM + j] = c;
        if (coords_out) coords_out[hit * DIM + j] = c;
    }
}

// AoS -> SoA + per-hit norm
__global__ __launch_bounds__(256)
void k_soa()
{
    int i = blockIdx.x * 256 + threadIdx.x;
    if (i >= NHITS) return;
    float4 c = *(const float4*)&g_coords[(size_t)i * 4];
    g_cx[i] = c.x; g_cy[i] = c.y; g_cz[i] = c.z; g_cw[i] = c.w;
    g_cn[i] = ((c.x * c.x + c.y * c.y) + c.z * c.z) + c.w * c.w;
}

// ---------------------------------------------------------------------------
// K2: per-event exact KNN, one thread per query.
//  - heap seeded with candidates 0..39 (direct placement + one heapify), so
//    the filter threshold is finite from the start (no append storm)
//  - hot loop is branch-free: packed f32x2 distance math, unconditional ring
//    store + predicated pend bump; only a uniform ballot'd flush branch
//  - flush rechecks the exact 64-bit key vs live root and skips self -> exact
// ---------------------------------------------------------------------------
#define KNN_T    128   // threads per block
#define RING_CAP 8

__device__ __forceinline__ ull heap_replace(ull (*hp)[KNN_T], int tid, ull key)
{
    int s = 0;
    ull rootval = key;
#pragma unroll
    for (int lvl = 0; lvl < 3; lvl++) {
        int c0 = 4 * s + 1;
        if (c0 >= KNN_K) break;
        ull k0 = hp[c0][tid];
        ull k1 = (c0 + 1 < KNN_K) ? hp[c0 + 1][tid] : 0ull;
        ull k2 = (c0 + 2 < KNN_K) ? hp[c0 + 2][tid] : 0ull;
        ull k3 = (c0 + 3 < KNN_K) ? hp[c0 + 3][tid] : 0ull;
        int ci = c0; ull ck = k0;
        if (k1 > ck) { ck = k1; ci = c0 + 1; }
        if (k2 > ck) { ck = k2; ci = c0 + 2; }
        if (k3 > ck) { ck = k3; ci = c0 + 3; }
        if (ck > key) {
            hp[s][tid] = ck;
            if (lvl == 0) rootval = ck;
            s = ci;
        } else break;
    }
    hp[s][tid] = key;
    return rootval;
}

__device__ __forceinline__ void heap_sift(ull (*hp)[KNN_T], int tid, ull key, int n)
{
    int s = 0;
    while (true) {
        int c0 = 4 * s + 1;
        if (c0 >= n) break;
        ull k0 = hp[c0][tid];
        ull k1 = (c0 + 1 < n) ? hp[c0 + 1][tid] : 0ull;
        ull k2 = (c0 + 2 < n) ? hp[c0 + 2][tid] : 0ull;
        ull k3 = (c0 + 3 < n) ? hp[c0 + 3][tid] : 0ull;
        int ci = c0; ull ck = k0;
        if (k1 > ck) { ck = k1; ci = c0 + 1; }
        if (k2 > ck) { ck = k2; ci = c0 + 2; }
        if (k3 > ck) { ck = k3; ci = c0 + 3; }
        if (ck > key) { hp[s][tid] = ck; s = ci; }
        else break;
    }
    hp[s][tid] = key;
}

// unflip: recover float bits from order-flipped encoding
__device__ __forceinline__ float key_to_dist(unsigned int b)
{
    unsigned int m = (unsigned int)((int)b >> 31);
    b ^= (m & 0x80000000u) | (~m);
    return __uint_as_float(b);
}

__global__ __launch_bounds__(KNN_T)
void k_knn(float* __restrict__ nidx_out,   // may be null (float-cast indices)
           float* __restrict__ dist_out)   // may be null
{
    __shared__ ull hp[KNN_K][KNN_T];       // 40*128*8 = 40960 B
    __shared__ ull ring[RING_CAP][KNN_T];  //  8*128*8 =  8192 B  (total 49152)

    int ev   = blockIdx.y;
    int base = ev * V_EV;
    int tid  = threadIdx.x;
    int q    = blockIdx.x * KNN_T + tid;
    bool act = (q < V_EV);
    int qcl  = act ? q : 0;   // clamped for safe loads; inactive lanes write nothing

    const float* px = &g_cx[base];
    const float* py = &g_cy[base];
    const float* pz = &g_cz[base];
    const float* pw = &g_cw[base];
    const float* pn = &g_cn[base];

    float qx = __ldg(px + qcl);
    float qy = __ldg(py + qcl);
    float qz = __ldg(pz + qcl);
    float qw = __ldg(pw + qcl);
    float qs = __ldg(pn + qcl);

    // ---- seed heap with candidates 0..39 (same rounding as hot loop) ----
#pragma unroll 8
    for (int w = 0; w < KNN_K; w++) {
        float cx = __ldg(px + w), cy = __ldg(py + w);
        float cz = __ldg(pz + w), cw = __ldg(pw + w);
        float nn = __ldg(pn + w);
        float dot = qx * cx;
        dot = fmaf(qy, cy, dot);
        dot = fmaf(qz, cz, dot);
        dot = fmaf(qw, cw, dot);
        float d = fmaf(-2.0f, dot, qs + nn);
        unsigned int b = __float_as_uint(d);
        b ^= (unsigned int)(((int)b >> 31) | 0x80000000);
        ull key = ((ull)b << 32) | (unsigned int)w;
        if (w == qcl) key = ~0ull;    // self -> sentinel (displaced later)
        hp[w][tid] = key;
    }
    // heapify (parents are indices 0..9 in the 4-ary heap of 40)
#pragma unroll 1
    for (int s = 9; s >= 0; s--) {
        // sift element s down within hp[0..39]
        ull key = hp[s][tid];
        int cur = s;
        while (true) {
            int c0 = 4 * cur + 1;
            if (c0 >= KNN_K) break;
            ull k0 = hp[c0][tid];
            ull k1 = (c0 + 1 < KNN_K) ? hp[c0 + 1][tid] : 0ull;
            ull k2 = (c0 + 2 < KNN_K) ? hp[c0 + 2][tid] : 0ull;
            ull k3 = (c0 + 3 < KNN_K) ? hp[c0 + 3][tid] : 0ull;
            int ci = c0; ull ck = k0;
            if (k1 > ck) { ck = k1; ci = c0 + 1; }
            if (k2 > ck) { ck = k2; ci = c0 + 2; }
            if (k3 > ck) { ck = k3; ci = c0 + 3; }
            if (ck > key) { hp[cur][tid] = ck; cur = ci; }
            else break;
        }
        hp[cur][tid] = key;
    }

    ull   thr   = hp[0][tid];
    float thr_f = (thr == ~0ull) ? INFINITY : key_to_dist((unsigned int)(thr >> 32));

    ull qx2 = f2_bcast(qx), qy2 = f2_bcast(qy);
    ull qz2 = f2_bcast(qz), qw2 = f2_bcast(qw);
    ull qs2 = f2_bcast(qs);
    ull m2  = f2_bcast(-2.0f);

    int pend = 0;

    // main loop over candidates 40..2999 (2960 = 740 groups of 4)
    for (int w0 = KNN_K; w0 < V_EV; w0 += 4) {
        ulonglong2 X = *(const ulonglong2*)(px + w0);  // (x0,x1),(x2,x3)
        ulonglong2 Y = *(const ulonglong2*)(py + w0);
        ulonglong2 Z = *(const ulonglong2*)(pz + w0);
        ulonglong2 W = *(const ulonglong2*)(pw + w0);
        ulonglong2 N = *(const ulonglong2*)(pn + w0);

        ull dot01 = f2_mul(qx2, X.x);
        dot01 = f2_fma(qy2, Y.x, dot01);
        dot01 = f2_fma(qz2, Z.x, dot01);
        dot01 = f2_fma(qw2, W.x, dot01);
        ull d01 = f2_fma(m2, dot01, f2_add(qs2, N.x));

        ull dot23 = f2_mul(qx2, X.y);
        dot23 = f2_fma(qy2, Y.y, dot23);
        dot23 = f2_fma(qz2, Z.y, dot23);
        dot23 = f2_fma(qw2, W.y, dot23);
        ull d23 = f2_fma(m2, dot23, f2_add(qs2, N.y));

        float d0, d1, d2, d3;
        f2_unpack(d01, d0, d1);
        f2_unpack(d23, d2, d3);

        // branch-free append: unconditional store, predicated bump
#pragma unroll
        for (int u = 0; u < 4; u++) {
            float d = (u == 0) ? d0 : (u == 1) ? d1 : (u == 2) ? d2 : d3;
            unsigned int bb = __float_as_uint(d);
            bb ^= (unsigned int)(((int)bb >> 31) | 0x80000000);
            ring[pend & (RING_CAP - 1)][tid] =
                ((ull)bb << 32) | (unsigned int)(w0 + u);
            pend += (d <= thr_f);
        }

        // flush when any lane's ring is near capacity (can gain 4/group)
        if (__any_sync(0xffffffffu, pend > RING_CAP - 4)) {
#pragma unroll 1
            for (int j = 0; j < pend; j++) {
                ull key = ring[j][tid];
                if ((unsigned int)key == (unsigned int)q) continue;  // self
                if (key < thr) thr = heap_replace(hp, tid, key);
            }
            pend = 0;
            thr_f = (thr == ~0ull) ? INFINITY
                                   : key_to_dist((unsigned int)(thr >> 32));
        }
    }

    // final flush
#pragma unroll 1
    for (int j = 0; j < pend; j++) {
        ull key = ring[j][tid];
        if ((unsigned int)key == (unsigned int)q) continue;
        if (key < thr) thr = heap_replace(hp, tid, key);
    }

    if (!act) return;

    // heapsort -> hp[0..39] ascending by (dist, idx)
    for (int n = KNN_K - 1; n > 0; n--) {
        ull top  = hp[0][tid];
        ull last = hp[n][tid];
        hp[n][tid] = top;
        heap_sift(hp, tid, last, n);
    }

    size_t rowoff = (size_t)(base + q) * KNN_K;
#pragma unroll 8
    for (int k = 0; k < KNN_K; k++) {
        ull key = hp[k][tid];
        unsigned int widx = (unsigned int)key;
        float dd = fmaxf(key_to_dist((unsigned int)(key >> 32)), 0.0f);
        int gidx = base + (int)widx;
        g_nidx[rowoff + k] = gidx;
        g_dist[rowoff + k] = dd;
        if (nidx_out) nidx_out[rowoff + k] = (float)gidx;
        if (dist_out) dist_out[rowoff + k] = dd;
    }
}

// ---------------------------------------------------------------------------
// K3: aggregation. a = [mean_k(f_nbr*w)-f, max_k(f_nbr*w)-f, x]  [N,192]
// ---------------------------------------------------------------------------
__global__ __launch_bounds__(256)
void k_agg(const float* __restrict__ x)
{
    __shared__ float wsh[4][KNN_K];
    __shared__ int   nsh[4][KNN_K];
    int h = threadIdx.x >> 6;
    int p = threadIdx.x & 63;
    int hit = blockIdx.x * 4 + h;

    if (hit < NHITS && p < KNN_K) {
        float dd = g_dist[(size_t)hit * KNN_K + p];
        wsh[h][p] = expf(-10.0f * dd);
        nsh[h][p] = g_nidx[(size_t)hit * KNN_K + p];
    }
    __syncthreads();
    if (hit >= NHITS) return;

    float acc = 0.0f;
    float mx = -INFINITY;
#pragma unroll 8
    for (int k = 0; k < KNN_K; k++) {
        float f = g_feat[(size_t)nsh[h][k] * PROP + p];
        float v = f * wsh[h][k];
        acc += v;
        mx = fmaxf(mx, v);
    }
    float fs = g_feat[(size_t)hit * PROP + p];
    float* arow = &g_a[(size_t)hit * AIN];
    arow[p]        = acc / (float)KNN_K - fs;
    arow[PROP + p] = mx - fs;
    arow[2 * PROP + p] = x[hit * FIN + p];
}

// ---------------------------------------------------------------------------
// K4: out = tanh(a @ W_out + b_out), [60000,192] x [192,128].
// ---------------------------------------------------------------------------
#define GM 128
#define GK 16

__global__ __launch_bounds__(256)
void k_gemm(const float* __restrict__ W, const float* __restrict__ bias,
            float* __restrict__ out)
{
    __shared__ float As[GK][GM + 4];
    __shared__ float Bs[GK][FOUT];

    int tid = threadIdx.x;
    int tx = tid & 15;
    int ty = tid >> 4;
    int rowBase = blockIdx.x * GM;

    float acc[8][8];
#pragma unroll
    for (int i = 0; i < 8; i++)
#pragma unroll
        for (int j = 0; j < 8; j++) acc[i][j] = 0.0f;

    for (int kt = 0; kt < AIN; kt += GK) {
#pragma unroll
        for (int l = 0; l < 2; l++) {
            int id = tid + l * 256;
            int r = id >> 2;
            int c4 = (id & 3) * 4;
            int grow = rowBase + r;
            float4 v = make_float4(0.f, 0.f, 0.f, 0.f);
            if (grow < NHITS)
                v = *(const float4*)&g_a[(size_t)grow * AIN + kt + c4];
            As[c4 + 0][r] = v.x;
            As[c4 + 1][r] = v.y;
            As[c4 + 2][r] = v.z;
            As[c4 + 3][r] = v.w;
        }
#pragma unroll
        for (int l = 0; l < 2; l++) {
            int id = tid + l * 256;
            int r = id >> 5;
            int c = (id & 31) * 4;
            *(float4*)&Bs[r][c] = *(const float4*)&W[(size_t)(kt + r) * FOUT + c];
        }
        __syncthreads();

#pragma unroll
        for (int k = 0; k < GK; k++) {
            float4 a0 = *(const float4*)&As[k][ty * 8];
            float4 a1 = *(const float4*)&As[k][ty * 8 + 4];
            float4 b0 = *(const float4*)&Bs[k][tx * 8];
            float4 b1 = *(const float4*)&Bs[k][tx * 8 + 4];
            float a[8] = {a0.x, a0.y, a0.z, a0.w, a1.x, a1.y, a1.z, a1.w};
            float b[8] = {b0.x, b0.y, b0.z, b0.w, b1.x, b1.y, b1.z, b1.w};
#pragma unroll
            for (int i = 0; i < 8; i++)
#pragma unroll
                for (int j = 0; j < 8; j++)
                    acc[i][j] += a[i] * b[j];
        }
        __syncthreads();
    }

    float bv[8];
#pragma unroll
    for (int j = 0; j < 8; j++) bv[j] = bias[tx * 8 + j];

#pragma unroll
    for (int i = 0; i < 8; i++) {
        int grow = rowBase + ty * 8 + i;
        if (grow < NHITS) {
#pragma unroll
            for (int j = 0; j < 8; j++)
                out[(size_t)grow * FOUT + tx * 8 + j] = tanhf(acc[i][j] + bv[j]);
        }
    }
}

// ---------------------------------------------------------------------------
// launch
// ---------------------------------------------------------------------------
extern "C" void kernel_launch(void* const* d_in, const int* in_sizes, int n_in,
                              void* d_out, int out_size)
{
    const float* x  = (const float*)d_in[0];
    const float* Wp = (const float*)d_in[2];
    const float* bp = (const float*)d_in[3];
    const float* Ws = (const float*)d_in[4];
    const float* bs = (const float*)d_in[5];
    const float* Wo = (const float*)d_in[6];
    const float* bo = (const float*)d_in[7];

    float* out = (float*)d_out;

    const int full_sz = NHITS * (FOUT + DIM + KNN_K + KNN_K);
    bool full = (out_size == full_sz);
    float* coords_out = full ? out + (size_t)NHITS * FOUT : nullptr;
    float* nidx_out   = full ? coords_out + (size_t)NHITS * DIM : nullptr;
    float* dist_out   = full ? nidx_out + (size_t)NHITS * KNN_K : nullptr;

    k_transform<<<NHITS / 4, 256>>>(x, Wp, bp, Ws, bs, coords_out);
    k_soa<<<(NHITS + 255) / 256, 256>>>();
    k_knn<<<dim3((V_EV + KNN_T - 1) / KNN_T, B_EV), KNN_T>>>(nidx_out, dist_out);
    k_agg<<<NHITS / 4, 256>>>(x);
    k_gemm<<<(NHITS + GM - 1) / GM, 256>>>(Wo, bo, out);
}